// round 12
// baseline (speedup 1.0000x reference)
#include <cuda_runtime.h>
#include <cuda_bf16.h>
#include <stdint.h>

#define BATCH 32
#define NSUBJ 512
#define NOBJ  512
#define NCLS  30
#define MAXK  15

__device__ unsigned g_maxbits;                       // max coord bits (monotone)
__device__ unsigned g_done[BATCH];                   // per-image class counter (monotone)
__device__ unsigned long long g_sub[BATCH][NSUBJ];   // kept? key : 0
__device__ unsigned long long g_obj[BATCH][NOBJ];

__device__ __forceinline__ unsigned long long mkkey(float s, unsigned p) {
    return ((unsigned long long)__float_as_uint(s) << 32) |
           (unsigned long long)(0xFFFFFFFFu - p);
}

// warp-wide OR of 64-bit via REDUX
__device__ __forceinline__ unsigned long long warp_or64(unsigned long long v) {
    unsigned lo = __reduce_or_sync(0xFFFFFFFFu, (unsigned)v);
    unsigned hi = __reduce_or_sync(0xFFFFFFFFu, (unsigned)(v >> 32));
    return ((unsigned long long)hi << 32) | lo;
}

// Per-warp workspace, phase-aliased: keys (scan/rank) then boxr (adjacency)
union WS {
    unsigned long long keys[128];
    float4 boxr[64];
};

// ---------------------------------------------------------------------------
// Kernel A: global max over all box coords. 128 blocks x 128 threads.
// ---------------------------------------------------------------------------
__global__ __launch_bounds__(128) void maxk(const float4* __restrict__ a4,
                                            const float4* __restrict__ b4) {
    const int gi = blockIdx.x * 128 + threadIdx.x;   // 16384 threads == 16384 float4/array
    float4 v = a4[gi];
    float m = fmaxf(fmaxf(v.x, v.y), fmaxf(v.z, v.w));
    v = b4[gi];
    m = fmaxf(m, fmaxf(fmaxf(v.x, v.y), fmaxf(v.z, v.w)));
    // positive coords: float bit order == value order; deterministic across replays
    unsigned mb = __reduce_max_sync(0xFFFFFFFFu, __float_as_uint(m));
    if ((threadIdx.x & 31) == 0) atomicMax(&g_maxbits, mb);
}

// ---------------------------------------------------------------------------
// Kernel B: one warp per (image, class) NMS; image-completing warp selects.
// 120 blocks x 256 threads = 960 warps.
// ---------------------------------------------------------------------------
__global__ __launch_bounds__(256) void nmssel(
    const float4* __restrict__ sbx, const float* __restrict__ ssc, const int* __restrict__ slb,
    const float4* __restrict__ obx_g, const float* __restrict__ osc, const int* __restrict__ olb,
    float* __restrict__ out)
{
    __shared__ WS ws[8];
    __shared__ float s_area[8][64];

    const int tid  = threadIdx.x;
    const int wid  = tid >> 5;
    const int lane = tid & 31;
    const unsigned ltm = (1u << lane) - 1u;

    const int g = blockIdx.x * 8 + wid;          // 960 = 32*30 exactly
    const int b = g / NCLS;
    const int c = g - b * NCLS;
    WS& W = ws[wid];

    const float mp1 = __fadd_rn(__uint_as_float(__ldcg(&g_maxbits)), 1.0f);

    // ---- scan: active members of class c ----
    const int4*   lb4s = (const int4*)(slb + b * NSUBJ);
    const int4*   lb4o = (const int4*)(olb + b * NOBJ);
    const float4* sc4s = (const float4*)(ssc + b * NSUBJ);
    const float4* sc4o = (const float4*)(osc + b * NOBJ);

    int base = 0;
    #pragma unroll
    for (int ch = 0; ch < 8; ++ch) {
        int4   L = (ch < 4) ? lb4s[ch * 32 + lane] : lb4o[(ch - 4) * 32 + lane];
        float4 S = (ch < 4) ? sc4s[ch * 32 + lane] : sc4o[(ch - 4) * 32 + lane];
        bool m0 = (L.x == c) && (S.x >= 0.2f);
        bool m1 = (L.y == c) && (S.y >= 0.2f);
        bool m2 = (L.z == c) && (S.z >= 0.2f);
        bool m3 = (L.w == c) && (S.w >= 0.2f);
        unsigned b0 = __ballot_sync(0xFFFFFFFFu, m0);
        unsigned b1 = __ballot_sync(0xFFFFFFFFu, m1);
        unsigned b2 = __ballot_sync(0xFFFFFFFFu, m2);
        unsigned b3 = __ballot_sync(0xFFFFFFFFu, m3);
        int pre = __popc(b0 & ltm) + __popc(b1 & ltm) +
                  __popc(b2 & ltm) + __popc(b3 & ltm);
        unsigned pb = (unsigned)(ch * 128 + lane * 4);
        int slot = base + pre;
        if (m0) { if (slot < 128) W.keys[slot] = mkkey(S.x, pb + 0); slot++; }
        if (m1) { if (slot < 128) W.keys[slot] = mkkey(S.y, pb + 1); slot++; }
        if (m2) { if (slot < 128) W.keys[slot] = mkkey(S.z, pb + 2); slot++; }
        if (m3) { if (slot < 128) W.keys[slot] = mkkey(S.w, pb + 3); slot++; }
        base += __popc(b0) + __popc(b1) + __popc(b2) + __popc(b3);
    }
    const int kc = (base < 128) ? base : 128;
    __syncwarp();

    if (kc > 0 && kc <= 64) {
        const int j0 = lane, j1 = lane + 32;
        const bool v0 = (j0 < kc), v1 = (j1 < kc);

        // own slot keys -> concat indices; box loads issue NOW (overlap rank)
        unsigned long long k0 = v0 ? W.keys[j0] : 0ull;
        unsigned long long k1 = v1 ? W.keys[j1] : 0ull;
        unsigned p0 = 0, p1 = 0;
        float4 bx0 = make_float4(0.f, 0.f, 0.f, 0.f), bx1 = bx0;
        if (v0) {
            p0 = 0xFFFFFFFFu - (unsigned)(k0 & 0xFFFFFFFFull);
            bx0 = (p0 < NSUBJ) ? sbx[b * NSUBJ + p0] : obx_g[b * NOBJ + p0 - NSUBJ];
        }
        if (v1) {
            p1 = 0xFFFFFFFFu - (unsigned)(k1 & 0xFFFFFFFFull);
            bx1 = (p1 < NSUBJ) ? sbx[b * NSUBJ + p1] : obx_g[b * NOBJ + p1 - NSUBJ];
        }

        // ---- ranks (descending key): r = #{q : key_q > key_mine} ----
        int r0 = 0, r1 = 0;
        for (int q = 0; q < kc; ++q) {
            unsigned long long kq = W.keys[q];
            r0 += (kq > k0);
            r1 += (kq > k1);
        }
        __syncwarp();                            // key reads done (boxr alias next)

        // ---- offset boxes + areas, written at RANK position ----
        const float off = __fmul_rn((float)c, mp1);
        float4 c0 = make_float4(0.f, 0.f, 0.f, 0.f), c1 = c0;
        float a0 = 0.f, a1 = 0.f;
        if (v0) {
            c0.x = __fadd_rn(bx0.x, off); c0.y = __fadd_rn(bx0.y, off);
            c0.z = __fadd_rn(bx0.z, off); c0.w = __fadd_rn(bx0.w, off);
            a0 = __fmul_rn(__fsub_rn(c0.z, c0.x), __fsub_rn(c0.w, c0.y));
            W.boxr[r0] = c0;  s_area[wid][r0] = a0;
        }
        if (v1) {
            c1.x = __fadd_rn(bx1.x, off); c1.y = __fadd_rn(bx1.y, off);
            c1.z = __fadd_rn(bx1.z, off); c1.w = __fadd_rn(bx1.w, off);
            a1 = __fmul_rn(__fsub_rn(c1.z, c1.x), __fsub_rn(c1.w, c1.y));
            W.boxr[r1] = c1;  s_area[wid][r1] = a1;
        }
        __syncwarp();

        // ---- adjacency rows for MY ranks (bits q > my rank, IoU > 0.5) ----
        unsigned long long row0 = 0, row1 = 0;
        if (v0) {
            for (int q = r0 + 1; q < kc; ++q) {
                float4 bq = W.boxr[q];
                float  aq = s_area[wid][q];
                float w = fmaxf(__fsub_rn(fminf(c0.z, bq.z), fmaxf(c0.x, bq.x)), 0.0f);
                float h = fmaxf(__fsub_rn(fminf(c0.w, bq.w), fmaxf(c0.y, bq.y)), 0.0f);
                float inter = __fmul_rn(w, h);
                float den = __fsub_rn(__fadd_rn(a0, aq), inter);
                if (__fdiv_rn(inter, den) > 0.5f) row0 |= 1ull << q;
            }
        }
        if (v1) {
            for (int q = r1 + 1; q < kc; ++q) {
                float4 bq = W.boxr[q];
                float  aq = s_area[wid][q];
                float w = fmaxf(__fsub_rn(fminf(c1.z, bq.z), fmaxf(c1.x, bq.x)), 0.0f);
                float h = fmaxf(__fsub_rn(fminf(c1.w, bq.w), fmaxf(c1.y, bq.y)), 0.0f);
                float inter = __fmul_rn(w, h);
                float den = __fsub_rn(__fadd_rn(a1, aq), inter);
                if (__fdiv_rn(inter, den) > 0.5f) row1 |= 1ull << q;
            }
        }

        // ---- Jacobi fixpoint on suppression DAG == greedy NMS ----
        const unsigned long long active = (kc >= 64) ? ~0ull : ((1ull << kc) - 1ull);
        unsigned long long keep = active;
        while (true) {
            unsigned long long contrib =
                ((v0 && ((keep >> r0) & 1ull)) ? row0 : 0ull) |
                ((v1 && ((keep >> r1) & 1ull)) ? row1 : 0ull);
            unsigned long long supp = warp_or64(contrib);
            unsigned long long nk = active & ~supp;
            if (nk == keep) break;
            keep = nk;
        }

        if (v0) {
            unsigned long long mk = ((keep >> r0) & 1ull) ? k0 : 0ull;
            if (p0 < NSUBJ) g_sub[b][p0] = mk; else g_obj[b][p0 - NSUBJ] = mk;
        }
        if (v1) {
            unsigned long long mk = ((keep >> r1) & 1ull) ? k1 : 0ull;
            if (p1 < NSUBJ) g_sub[b][p1] = mk; else g_obj[b][p1 - NSUBJ] = mk;
        }
    } else if (kc > 64) {
        // correctness-only serial fallback (effectively never on this data)
        if (lane == 0) {
            unsigned long long keys[128];
            float4 bxs[128];
            float  ars[128];
            unsigned char sup[128];
            const float off = __fmul_rn((float)c, mp1);
            for (int j = 0; j < kc; ++j) keys[j] = W.keys[j];
            for (int i = 0; i < kc - 1; ++i) {               // selection sort desc
                int bi_ = i;
                for (int j = i + 1; j < kc; ++j) if (keys[j] > keys[bi_]) bi_ = j;
                unsigned long long t = keys[i]; keys[i] = keys[bi_]; keys[bi_] = t;
            }
            for (int j = 0; j < kc; ++j) {
                unsigned p = 0xFFFFFFFFu - (unsigned)(keys[j] & 0xFFFFFFFFull);
                float4 bx = (p < NSUBJ) ? sbx[b * NSUBJ + p] : obx_g[b * NOBJ + p - NSUBJ];
                float4 o4;
                o4.x = __fadd_rn(bx.x, off); o4.y = __fadd_rn(bx.y, off);
                o4.z = __fadd_rn(bx.z, off); o4.w = __fadd_rn(bx.w, off);
                bxs[j] = o4;
                ars[j] = __fmul_rn(__fsub_rn(o4.z, o4.x), __fsub_rn(o4.w, o4.y));
                sup[j] = 0;
            }
            for (int i = 0; i < kc - 1; ++i) {
                if (sup[i]) continue;                         // all members active
                float4 bi_ = bxs[i]; float ai = ars[i];
                for (int j = i + 1; j < kc; ++j) {
                    if (sup[j]) continue;
                    float4 bj = bxs[j];
                    float w = fmaxf(__fsub_rn(fminf(bi_.z, bj.z), fmaxf(bi_.x, bj.x)), 0.0f);
                    float h = fmaxf(__fsub_rn(fminf(bi_.w, bj.w), fmaxf(bi_.y, bj.y)), 0.0f);
                    float inter = __fmul_rn(w, h);
                    float den = __fsub_rn(__fadd_rn(ai, ars[j]), inter);
                    if (__fdiv_rn(inter, den) > 0.5f) sup[j] = 1;
                }
            }
            for (int j = 0; j < kc; ++j) {
                unsigned p = 0xFFFFFFFFu - (unsigned)(keys[j] & 0xFFFFFFFFull);
                unsigned long long mk = sup[j] ? 0ull : keys[j];
                if (p < NSUBJ) g_sub[b][p] = mk; else g_obj[b][p - NSUBJ] = mk;
            }
        }
    }
    // kc == 0: nothing to write (slots stay 0)

    // ---- completion: last class warp of image b runs its selection ----
    __threadfence();
    unsigned old = 0;
    if (lane == 0) old = atomicAdd(&g_done[b], 1u);
    old = __shfl_sync(0xFFFFFFFFu, old, 0);
    if (old % NCLS != NCLS - 1) return;
    __threadfence();

    // ====== selection + output for image b: subjects & objects interleaved ==
    {
        unsigned long long kvS[16], kvO[16];
        #pragma unroll
        for (int i = 0; i < 8; ++i) {
            ulonglong2 t = __ldcg((const ulonglong2*)&g_sub[b][i * 64 + lane * 2]);
            kvS[i * 2 + 0] = t.x;  kvS[i * 2 + 1] = t.y;
            ulonglong2 u = __ldcg((const ulonglong2*)&g_obj[b][i * 64 + lane * 2]);
            kvO[i * 2 + 0] = u.x;  kvO[i * 2 + 1] = u.y;
        }

        // per-lane descending bitonic sorts (both sides interleaved for ILP)
        #pragma unroll
        for (unsigned kk = 2; kk <= 16; kk <<= 1) {
            #pragma unroll
            for (unsigned j = kk >> 1; j; j >>= 1) {
                #pragma unroll
                for (unsigned i = 0; i < 16; ++i) {
                    if ((i & j) == 0) {
                        unsigned l = i | j;
                        bool mx = ((i & kk) == 0);
                        unsigned long long a = kvS[i], cc = kvS[l];
                        unsigned long long hi = (a > cc) ? a : cc;
                        unsigned long long lo = (a > cc) ? cc : a;
                        kvS[i] = mx ? hi : lo;
                        kvS[l] = mx ? lo : hi;
                        a = kvO[i]; cc = kvO[l];
                        hi = (a > cc) ? a : cc;
                        lo = (a > cc) ? cc : a;
                        kvO[i] = mx ? hi : lo;
                        kvO[l] = mx ? lo : hi;
                    }
                }
            }
        }

        // top-15 extraction, both sides interleaved (keys unique)
        unsigned long long mykeyS = 0, mykeyO = 0;
        int ptrS = 0, ptrO = 0, nselS = 0, nselO = 0;
        #pragma unroll 1
        for (int it = 0; it < MAXK; ++it) {
            unsigned long long candS = (ptrS < 16) ? kvS[ptrS] : 0ull;
            unsigned long long candO = (ptrO < 16) ? kvO[ptrO] : 0ull;
            unsigned mhiS = __reduce_max_sync(0xFFFFFFFFu, (unsigned)(candS >> 32));
            unsigned mhiO = __reduce_max_sync(0xFFFFFFFFu, (unsigned)(candO >> 32));
            if ((mhiS | mhiO) == 0) break;
            unsigned cloS = ((unsigned)(candS >> 32) == mhiS) ? (unsigned)candS : 0u;
            unsigned cloO = ((unsigned)(candO >> 32) == mhiO) ? (unsigned)candO : 0u;
            unsigned mloS = __reduce_max_sync(0xFFFFFFFFu, cloS);
            unsigned mloO = __reduce_max_sync(0xFFFFFFFFu, cloO);
            if (mhiS != 0) {
                unsigned long long winS = ((unsigned long long)mhiS << 32) | mloS;
                if (candS == winS) ptrS++;
                if (lane == it) mykeyS = winS;
                nselS++;
            }
            if (mhiO != 0) {
                unsigned long long winO = ((unsigned long long)mhiO << 32) | mloO;
                if (candO == winO) ptrO++;
                if (lane == it) mykeyO = winO;
                nselO++;
            }
        }

        if (lane < MAXK) {
            const float* sbf = (const float*)sbx;
            const float* obf = (const float*)obx_g;
            float* Bo = out;
            float* So = out + BATCH * 2 * MAXK * 4;
            float* Lo = So + BATCH * 2 * MAXK;
            float* No = Lo + BATCH * 2 * MAXK;
            float* Vo = No + BATCH;

            #pragma unroll
            for (int w = 0; w < 2; ++w) {
                unsigned long long mykey = w ? mykeyO : mykeyS;
                const int k = w * MAXK + lane;
                const bool valid = (mykey != 0);
                float b0 = 0.f, b1 = 0.f, b2 = 0.f, b3 = 0.f, scv = 0.f;
                int lb = -1;
                if (valid) {
                    unsigned p = 0xFFFFFFFFu - (unsigned)(mykey & 0xFFFFFFFFull);
                    const float* bp;
                    if (p < NSUBJ) { bp = sbf + ((size_t)b * NSUBJ + p) * 4;          lb = slb[b * NSUBJ + p]; }
                    else           { bp = obf + ((size_t)b * NOBJ + (p - NSUBJ)) * 4; lb = olb[b * NOBJ + p - NSUBJ]; }
                    b0 = bp[0]; b1 = bp[1]; b2 = bp[2]; b3 = bp[3];
                    scv = __uint_as_float((unsigned)(mykey >> 32));
                }
                int o = b * (2 * MAXK) + k;
                Bo[o * 4 + 0] = b0;
                Bo[o * 4 + 1] = b1;
                Bo[o * 4 + 2] = b2;
                Bo[o * 4 + 3] = b3;
                So[o] = scv;
                Lo[o] = (float)lb;
                Vo[o] = valid ? 1.0f : 0.0f;
            }
            if (lane == 0) No[b] = (float)((nselS < MAXK) ? nselS : MAXK);
        }
    }
}

// ---------------------------------------------------------------------------
extern "C" void kernel_launch(void* const* d_in, const int* in_sizes, int n_in,
                              void* d_out, int out_size) {
    const float4* sbx = (const float4*)d_in[0];
    const float*  ssc = (const float*)d_in[1];
    const int*    slb = (const int*)d_in[2];
    const float4* obx = (const float4*)d_in[3];
    const float*  osc = (const float*)d_in[4];
    const int*    olb = (const int*)d_in[5];

    maxk<<<128, 128>>>(sbx, obx);
    nmssel<<<120, 256>>>(sbx, ssc, slb, obx, osc, olb, (float*)d_out);
}

// round 15
// speedup vs baseline: 1.1429x; 1.1429x over previous
#include <cuda_runtime.h>
#include <cuda_bf16.h>
#include <stdint.h>

#define BATCH 32
#define NSUBJ 512
#define NOBJ  512
#define NCLS  30
#define MAXK  15

#define GRID 120
#define TPB  256

__device__ unsigned g_maxbits;                       // max coord bits (monotone)
__device__ unsigned g_cnt;                           // phase-0 block counter (monotone)
__device__ unsigned g_done[BATCH];                   // per-image class counter (monotone)
__device__ unsigned long long g_sub[BATCH][NSUBJ];   // kept? key : 0
__device__ unsigned long long g_obj[BATCH][NOBJ];    // kept? key : 0

__device__ __forceinline__ unsigned long long mkkey(float s, unsigned p) {
    return ((unsigned long long)__float_as_uint(s) << 32) |
           (unsigned long long)(0xFFFFFFFFu - p);
}

// warp-wide OR of 64-bit via REDUX
__device__ __forceinline__ unsigned long long warp_or64(unsigned long long v) {
    unsigned lo = __reduce_or_sync(0xFFFFFFFFu, (unsigned)v);
    unsigned hi = __reduce_or_sync(0xFFFFFFFFu, (unsigned)(v >> 32));
    return ((unsigned long long)hi << 32) | lo;
}

// Per-warp workspace, phase-aliased: keys (scan/rank) then boxr (adjacency)
union WS {
    unsigned long long keys[128];
    float4 boxr[64];
};

// ---------------------------------------------------------------------------
// Fused kernel: slice-max + one warp per (image, class) NMS + inline selection
// 120 blocks x 256 threads = 960 warps.
// ---------------------------------------------------------------------------
__global__ __launch_bounds__(TPB) void nmssel(
    const float4* __restrict__ sbx, const float* __restrict__ ssc, const int* __restrict__ slb,
    const float4* __restrict__ obx_g, const float* __restrict__ osc, const int* __restrict__ olb,
    float* __restrict__ out)
{
    __shared__ WS ws[8];
    __shared__ float s_area[8][64];
    __shared__ unsigned s_tgt;

    const int tid  = threadIdx.x;
    const int wid  = tid >> 5;
    const int lane = tid & 31;
    const unsigned ltm = (1u << lane) - 1u;

    const int g = blockIdx.x * 8 + wid;          // 960 = 32*30 exactly
    const int b = g / NCLS;
    const int c = g - b * NCLS;
    WS& W = ws[wid];

    // =============== Phase 0: block-slice max of all box coords ============
    {
        float m = 0.0f;
        const int gi = blockIdx.x * TPB + tid;   // 30720 threads, 16384 float4/array
        if (gi < 16384) {
            float4 v = ((const float4*)sbx)[gi];
            m = fmaxf(m, fmaxf(fmaxf(v.x, v.y), fmaxf(v.z, v.w)));
            v = ((const float4*)obx_g)[gi];
            m = fmaxf(m, fmaxf(fmaxf(v.x, v.y), fmaxf(v.z, v.w)));
        }
        // positive coords: float bit order == value order; deterministic per replay
        unsigned mb = __reduce_max_sync(0xFFFFFFFFu, __float_as_uint(m));
        if (lane == 0) atomicMax(&g_maxbits, mb);
        __syncthreads();                         // all warps' atomicMax issued+ordered
        if (tid == 0) {
            __threadfence();                     // maxes visible before counter bump
            unsigned old = atomicAdd(&g_cnt, 1u);
            s_tgt = (old / GRID + 1u) * GRID;    // replay-safe monotonic target
        }
        __syncthreads();
    }
    const unsigned tgt = s_tgt;

    // ---- scan: active members of class c (validated R11 body) ----
    const int4*   lb4s = (const int4*)(slb + b * NSUBJ);
    const int4*   lb4o = (const int4*)(olb + b * NOBJ);
    const float4* sc4s = (const float4*)(ssc + b * NSUBJ);
    const float4* sc4o = (const float4*)(osc + b * NOBJ);

    int base = 0;
    #pragma unroll
    for (int ch = 0; ch < 8; ++ch) {
        int4   L = (ch < 4) ? lb4s[ch * 32 + lane] : lb4o[(ch - 4) * 32 + lane];
        float4 S = (ch < 4) ? sc4s[ch * 32 + lane] : sc4o[(ch - 4) * 32 + lane];
        bool m0 = (L.x == c) && (S.x >= 0.2f);
        bool m1 = (L.y == c) && (S.y >= 0.2f);
        bool m2 = (L.z == c) && (S.z >= 0.2f);
        bool m3 = (L.w == c) && (S.w >= 0.2f);
        unsigned b0 = __ballot_sync(0xFFFFFFFFu, m0);
        unsigned b1 = __ballot_sync(0xFFFFFFFFu, m1);
        unsigned b2 = __ballot_sync(0xFFFFFFFFu, m2);
        unsigned b3 = __ballot_sync(0xFFFFFFFFu, m3);
        int pre = __popc(b0 & ltm) + __popc(b1 & ltm) +
                  __popc(b2 & ltm) + __popc(b3 & ltm);
        unsigned pb = (unsigned)(ch * 128 + lane * 4);
        int slot = base + pre;
        if (m0) { if (slot < 128) W.keys[slot] = mkkey(S.x, pb + 0); slot++; }
        if (m1) { if (slot < 128) W.keys[slot] = mkkey(S.y, pb + 1); slot++; }
        if (m2) { if (slot < 128) W.keys[slot] = mkkey(S.z, pb + 2); slot++; }
        if (m3) { if (slot < 128) W.keys[slot] = mkkey(S.w, pb + 3); slot++; }
        base += __popc(b0) + __popc(b1) + __popc(b2) + __popc(b3);
    }
    const int kc = (base < 128) ? base : 128;
    __syncwarp();

    // ---- late poll: all blocks' phase-0 done (expected instant) ----
    while (__ldcg(&g_cnt) < tgt) { }
    __threadfence();
    const float mp1 = __fadd_rn(__uint_as_float(__ldcg(&g_maxbits)), 1.0f);

    if (kc > 0 && kc <= 64) {
        const int j0 = lane, j1 = lane + 32;
        const bool v0 = (j0 < kc), v1 = (j1 < kc);

        // ---- ranks (descending key): r = #{q : key_q > key_mine} ----
        unsigned long long k0 = v0 ? W.keys[j0] : 0ull;
        unsigned long long k1 = v1 ? W.keys[j1] : 0ull;
        int r0 = 0, r1 = 0;
        for (int q = 0; q < kc; ++q) {
            unsigned long long kq = W.keys[q];
            r0 += (kq > k0);
            r1 += (kq > k1);
        }
        __syncwarp();
        if (v0) W.keys[r0] = k0;                 // in-place krank
        if (v1) W.keys[r1] = k1;
        __syncwarp();
        unsigned long long kr0 = v0 ? W.keys[j0] : 0ull;
        unsigned long long kr1 = v1 ? W.keys[j1] : 0ull;
        __syncwarp();                            // krank reads done (boxr alias next)

        // ---- gather by rank: offset boxes + areas ----
        const float off = __fmul_rn((float)c, mp1);
        float4 c0 = make_float4(0.f, 0.f, 0.f, 0.f), c1 = c0;
        float a0 = 0.f, a1 = 0.f;
        unsigned p0 = 0, p1 = 0;
        if (v0) {
            p0 = 0xFFFFFFFFu - (unsigned)(kr0 & 0xFFFFFFFFull);
            float4 bx = (p0 < NSUBJ) ? sbx[b * NSUBJ + p0] : obx_g[b * NOBJ + p0 - NSUBJ];
            c0.x = __fadd_rn(bx.x, off); c0.y = __fadd_rn(bx.y, off);
            c0.z = __fadd_rn(bx.z, off); c0.w = __fadd_rn(bx.w, off);
            a0 = __fmul_rn(__fsub_rn(c0.z, c0.x), __fsub_rn(c0.w, c0.y));
            W.boxr[j0] = c0;  s_area[wid][j0] = a0;
        }
        if (v1) {
            p1 = 0xFFFFFFFFu - (unsigned)(kr1 & 0xFFFFFFFFull);
            float4 bx = (p1 < NSUBJ) ? sbx[b * NSUBJ + p1] : obx_g[b * NOBJ + p1 - NSUBJ];
            c1.x = __fadd_rn(bx.x, off); c1.y = __fadd_rn(bx.y, off);
            c1.z = __fadd_rn(bx.z, off); c1.w = __fadd_rn(bx.w, off);
            a1 = __fmul_rn(__fsub_rn(c1.z, c1.x), __fsub_rn(c1.w, c1.y));
            W.boxr[j1] = c1;  s_area[wid][j1] = a1;
        }
        __syncwarp();

        // ---- adjacency rows (bits q > my rank with IoU > 0.5) ----
        unsigned long long row0 = 0, row1 = 0;
        if (v0) {
            for (int q = j0 + 1; q < kc; ++q) {
                float4 bq = W.boxr[q];
                float  aq = s_area[wid][q];
                float w = fmaxf(__fsub_rn(fminf(c0.z, bq.z), fmaxf(c0.x, bq.x)), 0.0f);
                float h = fmaxf(__fsub_rn(fminf(c0.w, bq.w), fmaxf(c0.y, bq.y)), 0.0f);
                float inter = __fmul_rn(w, h);
                float den = __fsub_rn(__fadd_rn(a0, aq), inter);
                if (__fdiv_rn(inter, den) > 0.5f) row0 |= 1ull << q;
            }
        }
        if (v1) {
            for (int q = j1 + 1; q < kc; ++q) {
                float4 bq = W.boxr[q];
                float  aq = s_area[wid][q];
                float w = fmaxf(__fsub_rn(fminf(c1.z, bq.z), fmaxf(c1.x, bq.x)), 0.0f);
                float h = fmaxf(__fsub_rn(fminf(c1.w, bq.w), fmaxf(c1.y, bq.y)), 0.0f);
                float inter = __fmul_rn(w, h);
                float den = __fsub_rn(__fadd_rn(a1, aq), inter);
                if (__fdiv_rn(inter, den) > 0.5f) row1 |= 1ull << q;
            }
        }

        // ---- Jacobi fixpoint on suppression DAG == greedy NMS ----
        const unsigned long long active = (kc >= 64) ? ~0ull : ((1ull << kc) - 1ull);
        unsigned long long keep = active;
        while (true) {
            unsigned long long contrib =
                (((keep >> j0) & 1ull) ? row0 : 0ull) |
                (((keep >> j1) & 1ull) ? row1 : 0ull);
            unsigned long long supp = warp_or64(contrib);
            unsigned long long nk = active & ~supp;
            if (nk == keep) break;
            keep = nk;
        }

        if (v0) {
            unsigned long long mk = ((keep >> j0) & 1ull) ? kr0 : 0ull;
            if (p0 < NSUBJ) g_sub[b][p0] = mk; else g_obj[b][p0 - NSUBJ] = mk;
        }
        if (v1) {
            unsigned long long mk = ((keep >> j1) & 1ull) ? kr1 : 0ull;
            if (p1 < NSUBJ) g_sub[b][p1] = mk; else g_obj[b][p1 - NSUBJ] = mk;
        }
    } else if (kc > 64) {
        // correctness-only serial fallback (effectively never on this data)
        if (lane == 0) {
            unsigned long long keys[128];
            float4 bxs[128];
            float  ars[128];
            unsigned char sup[128];
            const float off = __fmul_rn((float)c, mp1);
            for (int j = 0; j < kc; ++j) keys[j] = W.keys[j];
            for (int i = 0; i < kc - 1; ++i) {               // selection sort desc
                int bi_ = i;
                for (int j = i + 1; j < kc; ++j) if (keys[j] > keys[bi_]) bi_ = j;
                unsigned long long t = keys[i]; keys[i] = keys[bi_]; keys[bi_] = t;
            }
            for (int j = 0; j < kc; ++j) {
                unsigned p = 0xFFFFFFFFu - (unsigned)(keys[j] & 0xFFFFFFFFull);
                float4 bx = (p < NSUBJ) ? sbx[b * NSUBJ + p] : obx_g[b * NOBJ + p - NSUBJ];
                float4 o4;
                o4.x = __fadd_rn(bx.x, off); o4.y = __fadd_rn(bx.y, off);
                o4.z = __fadd_rn(bx.z, off); o4.w = __fadd_rn(bx.w, off);
                bxs[j] = o4;
                ars[j] = __fmul_rn(__fsub_rn(o4.z, o4.x), __fsub_rn(o4.w, o4.y));
                sup[j] = 0;
            }
            for (int i = 0; i < kc - 1; ++i) {
                if (sup[i]) continue;                         // all members active
                float4 bi_ = bxs[i]; float ai = ars[i];
                for (int j = i + 1; j < kc; ++j) {
                    if (sup[j]) continue;
                    float4 bj = bxs[j];
                    float w = fmaxf(__fsub_rn(fminf(bi_.z, bj.z), fmaxf(bi_.x, bj.x)), 0.0f);
                    float h = fmaxf(__fsub_rn(fminf(bi_.w, bj.w), fmaxf(bi_.y, bj.y)), 0.0f);
                    float inter = __fmul_rn(w, h);
                    float den = __fsub_rn(__fadd_rn(ai, ars[j]), inter);
                    if (__fdiv_rn(inter, den) > 0.5f) sup[j] = 1;
                }
            }
            for (int j = 0; j < kc; ++j) {
                unsigned p = 0xFFFFFFFFu - (unsigned)(keys[j] & 0xFFFFFFFFull);
                unsigned long long mk = sup[j] ? 0ull : keys[j];
                if (p < NSUBJ) g_sub[b][p] = mk; else g_obj[b][p - NSUBJ] = mk;
            }
        }
    }
    // kc == 0: nothing to write (slots stay 0)

    // ---- completion: last class warp of image b runs its selection ----
    __threadfence();
    unsigned old = 0;
    if (lane == 0) old = atomicAdd(&g_done[b], 1u);
    old = __shfl_sync(0xFFFFFFFFu, old, 0);
    if (old % NCLS != NCLS - 1) return;
    __threadfence();

    // =============== selection + output for image b (R11 validated) ========
    #pragma unroll
    for (int w = 0; w < 2; ++w) {
        const unsigned long long* keys = w ? g_obj[b] : g_sub[b];

        unsigned long long kv[16];
        #pragma unroll
        for (int i = 0; i < 8; ++i) {
            ulonglong2 t = __ldcg((const ulonglong2*)&keys[i * 64 + lane * 2]);
            kv[i * 2 + 0] = t.x;
            kv[i * 2 + 1] = t.y;
        }

        // per-lane descending bitonic sort of 16 registers (no communication)
        #pragma unroll
        for (unsigned kk = 2; kk <= 16; kk <<= 1) {
            #pragma unroll
            for (unsigned j = kk >> 1; j; j >>= 1) {
                #pragma unroll
                for (unsigned i = 0; i < 16; ++i) {
                    if ((i & j) == 0) {
                        unsigned l = i | j;
                        bool mx = ((i & kk) == 0);     // lower index keeps max in desc runs
                        unsigned long long a = kv[i], cc = kv[l];
                        unsigned long long hi = (a > cc) ? a : cc;
                        unsigned long long lo = (a > cc) ? cc : a;
                        kv[i] = mx ? hi : lo;
                        kv[l] = mx ? lo : hi;
                    }
                }
            }
        }

        // top-15 extraction: pointer bump + 2-stage REDUX max (keys unique)
        unsigned long long mykey = 0;
        int ptr = 0;
        int nsel = MAXK;
        for (int it = 0; it < MAXK; ++it) {
            unsigned long long cand = (ptr < 16) ? kv[ptr] : 0ull;
            unsigned chi = (unsigned)(cand >> 32);
            unsigned mhi = __reduce_max_sync(0xFFFFFFFFu, chi);
            if (mhi == 0) { nsel = it; break; }     // all exhausted (keys have hi>0)
            unsigned clo = (chi == mhi) ? (unsigned)cand : 0u;
            unsigned mlo = __reduce_max_sync(0xFFFFFFFFu, clo);
            unsigned long long winner = ((unsigned long long)mhi << 32) | mlo;
            if (cand == winner) ptr++;              // unique winner lane advances
            if (lane == it) mykey = winner;
        }

        if (lane < MAXK) {
            const int k = w * MAXK + lane;
            const bool valid = (mykey != 0);
            float b0 = 0.f, b1 = 0.f, b2 = 0.f, b3 = 0.f, scv = 0.f;
            int lb = -1;
            if (valid) {
                unsigned p = 0xFFFFFFFFu - (unsigned)(mykey & 0xFFFFFFFFull);
                const float* sbf = (const float*)sbx;
                const float* obf = (const float*)obx_g;
                const float* bp;
                if (p < NSUBJ) { bp = sbf + ((size_t)b * NSUBJ + p) * 4;          lb = slb[b * NSUBJ + p]; }
                else           { bp = obf + ((size_t)b * NOBJ + (p - NSUBJ)) * 4; lb = olb[b * NOBJ + p - NSUBJ]; }
                b0 = bp[0]; b1 = bp[1]; b2 = bp[2]; b3 = bp[3];
                scv = __uint_as_float((unsigned)(mykey >> 32));
            }
            float* Bo = out;
            float* So = out + BATCH * 2 * MAXK * 4;
            float* Lo = So + BATCH * 2 * MAXK;
            float* No = Lo + BATCH * 2 * MAXK;
            float* Vo = No + BATCH;
            int o = b * (2 * MAXK) + k;
            Bo[o * 4 + 0] = b0;
            Bo[o * 4 + 1] = b1;
            Bo[o * 4 + 2] = b2;
            Bo[o * 4 + 3] = b3;
            So[o] = scv;
            Lo[o] = (float)lb;
            Vo[o] = valid ? 1.0f : 0.0f;
            if (w == 0 && lane == 0) No[b] = (float)nsel;
        }
    }
}

// ---------------------------------------------------------------------------
extern "C" void kernel_launch(void* const* d_in, const int* in_sizes, int n_in,
                              void* d_out, int out_size) {
    const float4* sbx = (const float4*)d_in[0];
    const float*  ssc = (const float*)d_in[1];
    const int*    slb = (const int*)d_in[2];
    const float4* obx = (const float4*)d_in[3];
    const float*  osc = (const float*)d_in[4];
    const int*    olb = (const int*)d_in[5];

    nmssel<<<GRID, TPB>>>(sbx, ssc, slb, obx, osc, olb, (float*)d_out);
}